// round 1
// baseline (speedup 1.0000x reference)
#include <cuda_runtime.h>
#include <math.h>

#define N       16384
#define IN_DIM  5000
#define HID     64
#define NCLS    4
#define NLEV    11
#define KSPLIT  16
#define KCHUNK  (N / KSPLIT)   /* 1024 */
#define KT      64
#define RROWS   64

// ---------------- device scratch (static, no allocations) ----------------
__device__ float g_h [N * HID];
__device__ float g_hs[N * HID];
__device__ float g_xr[N * HID];
__device__ float g_xz[N * HID];
__device__ float g_xh[N * HID];
__device__ int   g_order[N];
__device__ int   g_cnt[NLEV];
__device__ int   g_cur[NLEV];
__device__ int   g_off[NLEV + 1];

__device__ __forceinline__ float sigmoidf_(float x) {
    return 1.0f / (1.0f + expf(-x));
}

// ---------------- bookkeeping kernels ----------------
__global__ void k_init() {
    int t = threadIdx.x;
    if (t < NLEV) { g_cnt[t] = 0; g_cur[t] = 0; }
}

// zero g_h and g_hs (2 * 1,048,576 floats = 524,288 float4)
__global__ void k_zero() {
    int idx = blockIdx.x * blockDim.x + threadIdx.x;
    float4 z = make_float4(0.f, 0.f, 0.f, 0.f);
    const int NH4 = (N * HID) / 4;
    if (idx < NH4)               ((float4*)g_h )[idx]        = z;
    else if (idx < 2 * NH4)      ((float4*)g_hs)[idx - NH4]  = z;
}

__global__ void k_hist(const int* __restrict__ level) {
    int i = blockIdx.x * blockDim.x + threadIdx.x;
    if (i < N) atomicAdd(&g_cnt[level[i]], 1);
}

__global__ void k_scan() {
    g_off[0] = 0;
    for (int l = 0; l < NLEV; l++) g_off[l + 1] = g_off[l] + g_cnt[l];
}

__global__ void k_scatter(const int* __restrict__ level) {
    int i = blockIdx.x * blockDim.x + threadIdx.x;
    if (i < N) {
        int lv = level[i];
        int p  = atomicAdd(&g_cur[lv], 1);
        g_order[g_off[lv] + p] = i;
    }
}

// ---------------- fused embedding GEMM: x_hat = tfidf @ E, then xr/xz/xh ----------------
__global__ __launch_bounds__(256) void embed_kernel(
    const float* __restrict__ tfidf, const float* __restrict__ Ew,
    const float* __restrict__ Wr, const float* __restrict__ Wz,
    const float* __restrict__ Wh)
{
    __shared__ float shA[RROWS][KT + 4];   // tfidf tile, later x_hat tile
    __shared__ float shB[KT][HID];         // E tile, later W tile

    int t = threadIdx.x;
    int rowbase = blockIdx.x * RROWS;
    int cq = t & 15, rq = t >> 4;
    int c0 = cq * 4, r0 = rq * 4;

    float acc[4][4] = {};

    for (int k0 = 0; k0 < IN_DIM; k0 += KT) {
        __syncthreads();
        // tfidf tile [64 rows][64 k]
        #pragma unroll
        for (int i = 0; i < 4; i++) {
            int u = t + i * 256;
            int r = u >> 4, kk4 = (u & 15) * 4;
            int k = k0 + kk4;
            float4 v = make_float4(0.f, 0.f, 0.f, 0.f);
            const float* src = &tfidf[(size_t)(rowbase + r) * IN_DIM + k];
            if (k + 3 < IN_DIM) v = *(const float4*)src;
            else {
                float tmp[4] = {0.f, 0.f, 0.f, 0.f};
                #pragma unroll
                for (int m = 0; m < 4; m++) if (k + m < IN_DIM) tmp[m] = src[m];
                v = make_float4(tmp[0], tmp[1], tmp[2], tmp[3]);
            }
            *(float4*)&shA[r][kk4] = v;
        }
        // E tile [64 k][64 c]
        #pragma unroll
        for (int i = 0; i < 4; i++) {
            int u = t + i * 256;
            int kk = u >> 4, c4 = (u & 15) * 4;
            int k = k0 + kk;
            float4 v = make_float4(0.f, 0.f, 0.f, 0.f);
            if (k < IN_DIM) v = *(const float4*)&Ew[(size_t)k * HID + c4];
            *(float4*)&shB[kk][c4] = v;
        }
        __syncthreads();
        #pragma unroll 16
        for (int kk = 0; kk < KT; kk++) {
            float4 b = *(float4*)&shB[kk][c0];
            float a[4];
            #pragma unroll
            for (int i = 0; i < 4; i++) a[i] = shA[r0 + i][kk];
            #pragma unroll
            for (int i = 0; i < 4; i++) {
                acc[i][0] += a[i] * b.x; acc[i][1] += a[i] * b.y;
                acc[i][2] += a[i] * b.z; acc[i][3] += a[i] * b.w;
            }
        }
    }

    // epilogue: write x_hat tile to shA, then xr/xz/xh = x @ W
    __syncthreads();
    #pragma unroll
    for (int i = 0; i < 4; i++)
        *(float4*)&shA[r0 + i][c0] =
            make_float4(acc[i][0], acc[i][1], acc[i][2], acc[i][3]);

    const float* Ws[3]  = {Wr, Wz, Wh};
    float*       Os[3]  = {g_xr, g_xz, g_xh};
    #pragma unroll
    for (int w = 0; w < 3; w++) {
        __syncthreads();
        #pragma unroll
        for (int i = 0; i < 4; i++) {
            int u = t + i * 256;
            int kk = u >> 4, c4 = (u & 15) * 4;
            *(float4*)&shB[kk][c4] = *(const float4*)&Ws[w][(size_t)kk * HID + c4];
        }
        __syncthreads();
        float o[4][4] = {};
        #pragma unroll 16
        for (int kk = 0; kk < HID; kk++) {
            float4 b = *(float4*)&shB[kk][c0];
            float a[4];
            #pragma unroll
            for (int i = 0; i < 4; i++) a[i] = shA[r0 + i][kk];
            #pragma unroll
            for (int i = 0; i < 4; i++) {
                o[i][0] += a[i] * b.x; o[i][1] += a[i] * b.y;
                o[i][2] += a[i] * b.z; o[i][3] += a[i] * b.w;
            }
        }
        #pragma unroll
        for (int i = 0; i < 4; i++)
            *(float4*)&Os[w][(size_t)(rowbase + r0 + i) * HID + c0] =
                make_float4(o[i][0], o[i][1], o[i][2], o[i][3]);
    }
}

// ---------------- level-masked aggregation: hs[rows_j] = adj[rows_j,:] @ h ----------------
__global__ __launch_bounds__(256) void agg_kernel(const float* __restrict__ adj, int j)
{
    __shared__ float shH[KT][HID];         // h tile [k][c]
    __shared__ float shAj[RROWS][KT + 4];  // adj tile [row][k]
    __shared__ int   shRows[RROWS];

    int cnt = g_cnt[j];
    int rb  = blockIdx.x * RROWS;
    if (rb >= cnt) return;
    int off = g_off[j];
    int t   = threadIdx.x;

    if (t < RROWS) {
        int l = rb + t;
        shRows[t] = (l < cnt) ? g_order[off + l] : -1;
    }
    __syncthreads();

    int cq = t & 15, rq = t >> 4;
    int c0 = cq * 4, r0 = rq * 4;
    float acc[4][4] = {};

    int kbase = blockIdx.y * KCHUNK;
    for (int kt = 0; kt < KCHUNK / KT; kt++) {
        int k0 = kbase + kt * KT;
        __syncthreads();
        // h tile (dense K: rows with level<=j are zero, contribute nothing)
        #pragma unroll
        for (int i = 0; i < 4; i++) {
            int u = t + i * 256;
            int kk = u >> 4, c4 = (u & 15) * 4;
            *(float4*)&shH[kk][c4] = *(const float4*)&g_h[(size_t)(k0 + kk) * HID + c4];
        }
        // adj tile (gathered rows)
        #pragma unroll
        for (int i = 0; i < 4; i++) {
            int u = t + i * 256;
            int r = u >> 4, kk4 = (u & 15) * 4;
            int grow = shRows[r];
            float4 v = make_float4(0.f, 0.f, 0.f, 0.f);
            if (grow >= 0) v = *(const float4*)&adj[(size_t)grow * N + k0 + kk4];
            *(float4*)&shAj[r][kk4] = v;
        }
        __syncthreads();
        #pragma unroll 16
        for (int kk = 0; kk < KT; kk++) {
            float4 hv = *(float4*)&shH[kk][c0];
            float a[4];
            #pragma unroll
            for (int i = 0; i < 4; i++) a[i] = shAj[r0 + i][kk];
            #pragma unroll
            for (int i = 0; i < 4; i++) {
                acc[i][0] += a[i] * hv.x; acc[i][1] += a[i] * hv.y;
                acc[i][2] += a[i] * hv.z; acc[i][3] += a[i] * hv.w;
            }
        }
    }

    #pragma unroll
    for (int i = 0; i < 4; i++) {
        int grow = shRows[r0 + i];
        if (grow < 0) continue;
        float* dst = &g_hs[(size_t)grow * HID + c0];
        atomicAdd(dst + 0, acc[i][0]);
        atomicAdd(dst + 1, acc[i][1]);
        atomicAdd(dst + 2, acc[i][2]);
        atomicAdd(dst + 3, acc[i][3]);
    }
}

// ---------------- GRU cell for level-j rows ----------------
__global__ __launch_bounds__(256) void gru_kernel(
    const float* __restrict__ Ur, const float* __restrict__ Uz,
    const float* __restrict__ Uh, int j)
{
    __shared__ float shU [HID][HID + 1];
    __shared__ float shHs[32][HID + 1];
    __shared__ float shRh[32][HID + 1];
    __shared__ int   shRows[32];

    int cnt = g_cnt[j];
    int rb  = blockIdx.x * 32;
    if (rb >= cnt) return;
    int off = g_off[j];
    int t   = threadIdx.x;

    if (t < 32) shRows[t] = (rb + t < cnt) ? g_order[off + rb + t] : -1;
    __syncthreads();

    // load hs rows
    #pragma unroll
    for (int i = 0; i < 8; i++) {
        int u = t + i * 256;
        int r = u >> 6, cc = u & 63;
        int gr = shRows[r];
        shHs[r][cc] = (gr >= 0) ? g_hs[(size_t)gr * HID + cc] : 0.0f;
    }
    // load Ur
    #pragma unroll
    for (int i = 0; i < 16; i++) {
        int u = t + i * 256;
        shU[u >> 6][u & 63] = Ur[u];
    }
    __syncthreads();

    int c = t & 63, rg = t >> 6;
    float zv[8], hsv[8];

    // phase R: rj = sigmoid(xr + hs @ Ur);  shRh = rj * hs
    #pragma unroll
    for (int i = 0; i < 8; i++) {
        int r = rg + 4 * i;
        int gr = shRows[r];
        float s = 0.f;
        #pragma unroll 16
        for (int kk = 0; kk < HID; kk++) s += shHs[r][kk] * shU[kk][c];
        float rj = (gr >= 0) ? sigmoidf_(g_xr[(size_t)gr * HID + c] + s) : 0.0f;
        shRh[r][c] = rj * shHs[r][c];
    }
    __syncthreads();
    #pragma unroll
    for (int i = 0; i < 16; i++) { int u = t + i * 256; shU[u >> 6][u & 63] = Uz[u]; }
    __syncthreads();

    // phase Z: zj = sigmoid(xz + hs @ Uz)
    #pragma unroll
    for (int i = 0; i < 8; i++) {
        int r = rg + 4 * i;
        int gr = shRows[r];
        float s = 0.f;
        #pragma unroll 16
        for (int kk = 0; kk < HID; kk++) s += shHs[r][kk] * shU[kk][c];
        zv[i]  = (gr >= 0) ? sigmoidf_(g_xz[(size_t)gr * HID + c] + s) : 0.0f;
        hsv[i] = shHs[r][c];
    }
    __syncthreads();
    #pragma unroll
    for (int i = 0; i < 16; i++) { int u = t + i * 256; shU[u >> 6][u & 63] = Uh[u]; }
    __syncthreads();

    // phase H: hh = tanh(xh + (hs*rj) @ Uh);  h = (1-z)*hs + z*hh
    #pragma unroll
    for (int i = 0; i < 8; i++) {
        int r = rg + 4 * i;
        int gr = shRows[r];
        if (gr < 0) continue;
        float s = 0.f;
        #pragma unroll 16
        for (int kk = 0; kk < HID; kk++) s += shRh[r][kk] * shU[kk][c];
        float hh = tanhf(g_xh[(size_t)gr * HID + c] + s);
        float hj = (1.0f - zv[i]) * hsv[i] + zv[i] * hh;
        g_h[(size_t)gr * HID + c] = hj;
    }
}

// ---------------- root reduce + decode ----------------
__global__ void final_kernel(const float* __restrict__ dec_w,
                             const float* __restrict__ dec_b,
                             float* __restrict__ out)
{
    __shared__ float red[4][HID];
    __shared__ float root[HID];
    int t = threadIdx.x;
    int c = t & 63, q = t >> 6;
    int cnt = g_cnt[0], off = g_off[0];
    float s = 0.f;
    for (int l = q; l < cnt; l += 4) {
        int gr = g_order[off + l];
        s += g_h[(size_t)gr * HID + c];
    }
    red[q][c] = s;
    __syncthreads();
    if (t < HID) root[t] = red[0][t] + red[1][t] + red[2][t] + red[3][t];
    __syncthreads();
    if (t < NCLS) {
        float a = dec_b[t];
        #pragma unroll 16
        for (int k = 0; k < HID; k++) a += root[k] * dec_w[k * NCLS + t];
        out[t] = a;
    }
}

// ---------------- launch ----------------
extern "C" void kernel_launch(void* const* d_in, const int* in_sizes, int n_in,
                              void* d_out, int out_size)
{
    const float* adj   = (const float*)d_in[0];
    const float* tfidf = (const float*)d_in[1];
    const int*   level = (const int*)d_in[2];
    const float* Ew    = (const float*)d_in[3];
    const float* Wr    = (const float*)d_in[4];
    const float* Wz    = (const float*)d_in[5];
    const float* Ur    = (const float*)d_in[6];
    const float* Uz    = (const float*)d_in[7];
    const float* Wh    = (const float*)d_in[8];
    const float* Uh    = (const float*)d_in[9];
    const float* dw    = (const float*)d_in[10];
    const float* db    = (const float*)d_in[11];
    float* out = (float*)d_out;

    k_init<<<1, 32>>>();
    k_zero<<<2048, 256>>>();
    k_hist<<<64, 256>>>(level);
    k_scan<<<1, 1>>>();
    k_scatter<<<64, 256>>>(level);
    embed_kernel<<<N / RROWS, 256>>>(tfidf, Ew, Wr, Wz, Wh);
    for (int j = NLEV - 1; j >= 0; j--) {
        agg_kernel<<<dim3(N / RROWS, KSPLIT), 256>>>(adj, j);
        gru_kernel<<<N / 32, 256>>>(Ur, Uz, Uh, j);
    }
    final_kernel<<<1, 256>>>(dw, db, out);
}

// round 6
// speedup vs baseline: 2.0499x; 2.0499x over previous
#include <cuda_runtime.h>
#include <cuda_bf16.h>
#include <math.h>
#include <stdint.h>

#define N       16384
#define IN_DIM  5000
#define HID     64
#define NCLS    4
#define NLEV    11
#define KSPLIT  8
#define KCHUNK  (N / KSPLIT)               /* 2048 */
#define KT      64
#define STAGES_A (KCHUNK / KT)             /* 32 */
#define STAGES_E ((IN_DIM + KT - 1) / KT)  /* 79 */
#define RROWS   64

// ---------------- device scratch (static, no allocations) ----------------
__device__ float g_h  [N * HID];
__device__ float g_hs [N * HID];
__device__ float g_xr [N * HID];
__device__ float g_xz [N * HID];
__device__ float g_xh [N * HID];
__device__ __nv_bfloat16 g_hbh[N * HID];   // h hi
__device__ __nv_bfloat16 g_hbl[N * HID];   // h lo (residual)
__device__ int   g_order[N];
__device__ int   g_cnt[NLEV];
__device__ int   g_cur[NLEV];
__device__ int   g_off[NLEV + 1];

__device__ __forceinline__ float sigmoidf_(float x) {
    return 1.0f / (1.0f + expf(-x));
}

// ---------------- mma helpers ----------------
__device__ __forceinline__ uint32_t sptr(const void* p) {
    return (uint32_t)__cvta_generic_to_shared(p);
}
__device__ __forceinline__ void ldsm_x4(uint32_t* r, uint32_t addr) {
    asm volatile("ldmatrix.sync.aligned.m8n8.x4.shared.b16 {%0,%1,%2,%3}, [%4];"
                 : "=r"(r[0]), "=r"(r[1]), "=r"(r[2]), "=r"(r[3]) : "r"(addr));
}
__device__ __forceinline__ void ldsm_x4_t(uint32_t* r, uint32_t addr) {
    asm volatile("ldmatrix.sync.aligned.m8n8.x4.trans.shared.b16 {%0,%1,%2,%3}, [%4];"
                 : "=r"(r[0]), "=r"(r[1]), "=r"(r[2]), "=r"(r[3]) : "r"(addr));
}
__device__ __forceinline__ void mma_bf16(float* c, const uint32_t* a,
                                         uint32_t b0, uint32_t b1) {
    asm volatile("mma.sync.aligned.m16n8k16.row.col.f32.bf16.bf16.f32 "
                 "{%0,%1,%2,%3}, {%4,%5,%6,%7}, {%8,%9}, {%0,%1,%2,%3};"
                 : "+f"(c[0]), "+f"(c[1]), "+f"(c[2]), "+f"(c[3])
                 : "r"(a[0]), "r"(a[1]), "r"(a[2]), "r"(a[3]), "r"(b0), "r"(b1));
}
// split a pair of fp32 into bf16 hi pair + bf16 lo (residual) pair
__device__ __forceinline__ void split2(float x, float y, uint32_t& hi, uint32_t& lo) {
    __nv_bfloat162 h = __floats2bfloat162_rn(x, y);
    float rx = x - __bfloat162float(h.x);
    float ry = y - __bfloat162float(h.y);
    __nv_bfloat162 l = __floats2bfloat162_rn(rx, ry);
    union { __nv_bfloat162 h; uint32_t u; } ch, cl;
    ch.h = h; cl.h = l;
    hi = ch.u; lo = cl.u;
}

// ---------------- bookkeeping kernels ----------------
__global__ void k_init() {
    int t = threadIdx.x;
    if (t < NLEV) { g_cnt[t] = 0; g_cur[t] = 0; }
}

__global__ void k_zero() {
    int idx = blockIdx.x * blockDim.x + threadIdx.x;
    const int NH4 = (N * HID) / 4;     /* 262144 */
    const int HB4 = (N * HID) / 8;     /* 131072 */
    float4 z = make_float4(0.f, 0.f, 0.f, 0.f);
    if (idx < NH4)                          ((float4*)g_h  )[idx]                 = z;
    else if (idx < 2 * NH4)                 ((float4*)g_hs )[idx - NH4]           = z;
    else if (idx < 2 * NH4 + HB4)           ((float4*)g_hbh)[idx - 2 * NH4]       = z;
    else if (idx < 2 * NH4 + 2 * HB4)       ((float4*)g_hbl)[idx - 2 * NH4 - HB4] = z;
}

__global__ void k_hist(const int* __restrict__ level) {
    int i = blockIdx.x * blockDim.x + threadIdx.x;
    if (i < N) atomicAdd(&g_cnt[level[i]], 1);
}

__global__ void k_scan() {
    g_off[0] = 0;
    for (int l = 0; l < NLEV; l++) g_off[l + 1] = g_off[l] + g_cnt[l];
}

__global__ void k_scatter(const int* __restrict__ level) {
    int i = blockIdx.x * blockDim.x + threadIdx.x;
    if (i < N) {
        int lv = level[i];
        int p  = atomicAdd(&g_cur[lv], 1);
        g_order[g_off[lv] + p] = i;
    }
}

// ---------------- tile loaders (64 rows/k x 64 wide) ----------------
__device__ __forceinline__ void load_A_gather(float4* ar, const float* __restrict__ src,
                                              const int* shRows, int t, int k0) {
    #pragma unroll
    for (int i = 0; i < 4; i++) {
        int u = t + i * 256, r = u >> 4, kq = u & 15;
        int grow = shRows[r];
        float4 v = make_float4(0.f, 0.f, 0.f, 0.f);
        if (grow >= 0) v = *(const float4*)(src + (size_t)grow * N + k0 + kq * 4);
        ar[i] = v;
    }
}
__device__ __forceinline__ void load_A_dense(float4* ar, const float* __restrict__ src,
                                             int rowbase, int t, int k0) {
    #pragma unroll
    for (int i = 0; i < 4; i++) {
        int u = t + i * 256, r = u >> 4, kq = u & 15;
        int k = k0 + kq * 4;
        float4 v = make_float4(0.f, 0.f, 0.f, 0.f);
        const float* p = src + (size_t)(rowbase + r) * IN_DIM + k;
        if (k + 3 < IN_DIM) v = *(const float4*)p;
        else if (k < IN_DIM) {
            float tmp[4] = {0.f, 0.f, 0.f, 0.f};
            #pragma unroll
            for (int m = 0; m < 4; m++) if (k + m < IN_DIM) tmp[m] = p[m];
            v = make_float4(tmp[0], tmp[1], tmp[2], tmp[3]);
        }
        ar[i] = v;
    }
}
// h tiles (pre-split bf16): 64 k x 64 cols each -> 2 uint4/thread per tile
__device__ __forceinline__ void load_H(uint4* hh, uint4* hl, int t, int k0) {
    #pragma unroll
    for (int i = 0; i < 2; i++) {
        int u = t + i * 256, kr = u >> 3, q = u & 7;
        size_t idx = (size_t)(k0 + kr) * HID + q * 8;
        hh[i] = *(const uint4*)&g_hbh[idx];
        hl[i] = *(const uint4*)&g_hbl[idx];
    }
}
__device__ __forceinline__ void load_E(float4* er, const float* __restrict__ Ew,
                                       int t, int k0) {
    #pragma unroll
    for (int i = 0; i < 4; i++) {
        int u = t + i * 256, kr = u >> 4, kq = u & 15;
        int k = k0 + kr;
        float4 v = make_float4(0.f, 0.f, 0.f, 0.f);
        if (k < IN_DIM) v = *(const float4*)&Ew[(size_t)k * HID + kq * 4];
        er[i] = v;
    }
}

// compensated mma inner step: acc += ahi*bhi + ahi*blo + alo*bhi
#define MMA3(ACC, AHI, ALO, BH0, BH1, BL0, BL1) \
    do { mma_bf16(ACC, AHI, BH0, BH1); mma_bf16(ACC, AHI, BL0, BL1); \
         mma_bf16(ACC, ALO, BH0, BH1); } while (0)

// ---------------- level-masked aggregation via compensated bf16 MMA ----------------
__global__ __launch_bounds__(256) void agg_kernel(const float* __restrict__ adj, int j)
{
    __shared__ __align__(16) __nv_bfloat16 shAh[RROWS][KT + 8];
    __shared__ __align__(16) __nv_bfloat16 shAl[RROWS][KT + 8];
    __shared__ __align__(16) __nv_bfloat16 shBh[KT][HID + 8];
    __shared__ __align__(16) __nv_bfloat16 shBl[KT][HID + 8];
    __shared__ int shRows[RROWS];

    int cnt = g_cnt[j];
    int rb  = blockIdx.x * RROWS;
    if (rb >= cnt) return;
    int off = g_off[j];
    int t   = threadIdx.x;
    if (t < RROWS) shRows[t] = (rb + t < cnt) ? g_order[off + rb + t] : -1;
    __syncthreads();

    int lane = t & 31;
    int wm = (t >> 5) & 3;
    int wn = (t >> 5) >> 2;

    uint32_t aAddrH = sptr(&shAh[wm * 16 + (lane & 15)][(lane >> 4) << 3]);
    uint32_t aAddrL = sptr(&shAl[wm * 16 + (lane & 15)][(lane >> 4) << 3]);
    uint32_t bAddrH = sptr(&shBh[lane & 15][wn * 32 + ((lane >> 4) << 3)]);
    uint32_t bAddrL = sptr(&shBl[lane & 15][wn * 32 + ((lane >> 4) << 3)]);
    const int B_ROW = (HID + 8) * 2;   // 144 bytes

    const int kbase = blockIdx.y * KCHUNK;

    float4 ar[4];
    uint4  hh[2], hl[2];
    load_A_gather(ar, adj, shRows, t, kbase);
    load_H(hh, hl, t, kbase);

    float acc[4][4] = {};

    for (int s = 0; s < STAGES_A; s++) {
        #pragma unroll
        for (int i = 0; i < 4; i++) {
            int u = t + i * 256, r = u >> 4, kq = u & 15;
            uint32_t h0, l0, h1, l1;
            split2(ar[i].x, ar[i].y, h0, l0);
            split2(ar[i].z, ar[i].w, h1, l1);
            *(uint2*)&shAh[r][kq * 4] = make_uint2(h0, h1);
            *(uint2*)&shAl[r][kq * 4] = make_uint2(l0, l1);
        }
        #pragma unroll
        for (int i = 0; i < 2; i++) {
            int u = t + i * 256, kr = u >> 3, q = u & 7;
            *(uint4*)&shBh[kr][q * 8] = hh[i];
            *(uint4*)&shBl[kr][q * 8] = hl[i];
        }
        __syncthreads();
        if (s + 1 < STAGES_A) {
            int k0 = kbase + (s + 1) * KT;
            load_A_gather(ar, adj, shRows, t, k0);
            load_H(hh, hl, t, k0);
        }
        #pragma unroll
        for (int ks = 0; ks < KT / 16; ks++) {
            uint32_t ah[4], al[4];
            ldsm_x4(ah, aAddrH + ks * 32);
            ldsm_x4(al, aAddrL + ks * 32);
            uint32_t bh[4], bl[4];
            ldsm_x4_t(bh, bAddrH + ks * 16 * B_ROW);
            ldsm_x4_t(bl, bAddrL + ks * 16 * B_ROW);
            MMA3(acc[0], ah, al, bh[0], bh[1], bl[0], bl[1]);
            MMA3(acc[1], ah, al, bh[2], bh[3], bl[2], bl[3]);
            ldsm_x4_t(bh, bAddrH + ks * 16 * B_ROW + 32);
            ldsm_x4_t(bl, bAddrL + ks * 16 * B_ROW + 32);
            MMA3(acc[2], ah, al, bh[0], bh[1], bl[0], bl[1]);
            MMA3(acc[3], ah, al, bh[2], bh[3], bl[2], bl[3]);
        }
        __syncthreads();
    }

    int g = lane >> 2, tq = lane & 3;
    #pragma unroll
    for (int nb = 0; nb < 4; nb++) {
        int col = wn * 32 + nb * 8 + tq * 2;
        int r0 = wm * 16 + g;
        int gr0 = shRows[r0];
        if (gr0 >= 0) {
            atomicAdd(&g_hs[(size_t)gr0 * HID + col],     acc[nb][0]);
            atomicAdd(&g_hs[(size_t)gr0 * HID + col + 1], acc[nb][1]);
        }
        int gr1 = shRows[r0 + 8];
        if (gr1 >= 0) {
            atomicAdd(&g_hs[(size_t)gr1 * HID + col],     acc[nb][2]);
            atomicAdd(&g_hs[(size_t)gr1 * HID + col + 1], acc[nb][3]);
        }
    }
}

// ---------------- embedding via compensated bf16 MMA + fp32 W projections ----------------
__global__ __launch_bounds__(256) void embed_kernel(
    const float* __restrict__ tfidf, const float* __restrict__ Ew,
    const float* __restrict__ Wr, const float* __restrict__ Wz,
    const float* __restrict__ Wh)
{
    __shared__ __align__(16) unsigned char sraw[4 * 9216 + 256];
    __nv_bfloat16 (*shAh)[KT + 8]  = (__nv_bfloat16(*)[KT + 8])(sraw);
    __nv_bfloat16 (*shAl)[KT + 8]  = (__nv_bfloat16(*)[KT + 8])(sraw + 9216);
    __nv_bfloat16 (*shBh)[HID + 8] = (__nv_bfloat16(*)[HID + 8])(sraw + 18432);
    __nv_bfloat16 (*shBl)[HID + 8] = (__nv_bfloat16(*)[HID + 8])(sraw + 27648);
    float (*shX)[68] = (float(*)[68])sraw;              // 64x68 fp32 = 17408 B
    float (*shW)[64] = (float(*)[64])(sraw + 18432);    // 64x64 fp32 = 16384 B

    int t = threadIdx.x;
    int rowbase = blockIdx.x * RROWS;

    int lane = t & 31;
    int wm = (t >> 5) & 3;
    int wn = (t >> 5) >> 2;

    uint32_t aAddrH = sptr(&shAh[wm * 16 + (lane & 15)][(lane >> 4) << 3]);
    uint32_t aAddrL = sptr(&shAl[wm * 16 + (lane & 15)][(lane >> 4) << 3]);
    uint32_t bAddrH = sptr(&shBh[lane & 15][wn * 32 + ((lane >> 4) << 3)]);
    uint32_t bAddrL = sptr(&shBl[lane & 15][wn * 32 + ((lane >> 4) << 3)]);
    const int B_ROW = (HID + 8) * 2;

    float4 ar[4], er[4];
    load_A_dense(ar, tfidf, rowbase, t, 0);
    load_E(er, Ew, t, 0);

    float acc[4][4] = {};

    for (int s = 0; s < STAGES_E; s++) {
        #pragma unroll
        for (int i = 0; i < 4; i++) {
            int u = t + i * 256, r = u >> 4, kq = u & 15;
            uint32_t h0, l0, h1, l1;
            split2(ar[i].x, ar[i].y, h0, l0);
            split2(ar[i].z, ar[i].w, h1, l1);
            *(uint2*)&shAh[r][kq * 4] = make_uint2(h0, h1);
            *(uint2*)&shAl[r][kq * 4] = make_uint2(l0, l1);
        }
        #pragma unroll
        for (int i = 0; i < 4; i++) {
            int u = t + i * 256, kr = u >> 4, kq = u & 15;
            uint32_t h0, l0, h1, l1;
            split2(er[i].x, er[i].y, h0, l0);
            split2(er[i].z, er[i].w, h1, l1);
            *(uint2*)&shBh[kr][kq * 4] = make_uint2(h0, h1);
            *(uint2*)&shBl[kr][kq * 4] = make_uint2(l0, l1);
        }
        __syncthreads();
        if (s + 1 < STAGES_E) {
            int k0 = (s + 1) * KT;
            load_A_dense(ar, tfidf, rowbase, t, k0);
            load_E(er, Ew, t, k0);
        }
        #pragma unroll
        for (int ks = 0; ks < KT / 16; ks++) {
            uint32_t ah[4], al[4];
            ldsm_x4(ah, aAddrH + ks * 32);
            ldsm_x4(al, aAddrL + ks * 32);
            uint32_t bh[4], bl[4];
            ldsm_x4_t(bh, bAddrH + ks * 16 * B_ROW);
            ldsm_x4_t(bl, bAddrL + ks * 16 * B_ROW);
            MMA3(acc[0], ah, al, bh[0], bh[1], bl[0], bl[1]);
            MMA3(acc[1], ah, al, bh[2], bh[3], bl[2], bl[3]);
            ldsm_x4_t(bh, bAddrH + ks * 16 * B_ROW + 32);
            ldsm_x4_t(bl, bAddrL + ks * 16 * B_ROW + 32);
            MMA3(acc[2], ah, al, bh[0], bh[1], bl[0], bl[1]);
            MMA3(acc[3], ah, al, bh[2], bh[3], bl[2], bl[3]);
        }
        __syncthreads();
    }

    // x_hat fragments -> shX (fp32)
    int g = lane >> 2, tq = lane & 3;
    #pragma unroll
    for (int nb = 0; nb < 4; nb++) {
        int col = wn * 32 + nb * 8 + tq * 2;
        int r0 = wm * 16 + g;
        shX[r0][col]         = acc[nb][0];
        shX[r0][col + 1]     = acc[nb][1];
        shX[r0 + 8][col]     = acc[nb][2];
        shX[r0 + 8][col + 1] = acc[nb][3];
    }

    const float* Ws[3] = {Wr, Wz, Wh};
    float*       Os[3] = {g_xr, g_xz, g_xh};
    int cq = t & 15, rq = t >> 4;
    int c0 = cq * 4, r0 = rq * 4;
    #pragma unroll
    for (int w = 0; w < 3; w++) {
        __syncthreads();
        #pragma unroll
        for (int i = 0; i < 4; i++) {
            int u = t + i * 256;
            int kk = u >> 4, c4 = (u & 15) * 4;
            *(float4*)&shW[kk][c4] = *(const float4*)&Ws[w][(size_t)kk * HID + c4];
        }
        __syncthreads();
        float o[4][4] = {};
        #pragma unroll 16
        for (int kk = 0; kk < HID; kk++) {
            float4 b = *(float4*)&shW[kk][c0];
            float a[4];
            #pragma unroll
            for (int i = 0; i < 4; i++) a[i] = shX[r0 + i][kk];
            #pragma unroll
            for (int i = 0; i < 4; i++) {
                o[i][0] += a[i] * b.x; o[i][1] += a[i] * b.y;
                o[i][2] += a[i] * b.z; o[i][3] += a[i] * b.w;
            }
        }
        #pragma unroll
        for (int i = 0; i < 4; i++)
            *(float4*)&Os[w][(size_t)(rowbase + r0 + i) * HID + c0] =
                make_float4(o[i][0], o[i][1], o[i][2], o[i][3]);
    }
}

// ---------------- GRU cell for level-j rows ----------------
__global__ __launch_bounds__(256) void gru_kernel(
    const float* __restrict__ Ur, const float* __restrict__ Uz,
    const float* __restrict__ Uh, int j)
{
    __shared__ float shU [HID][HID + 1];
    __shared__ float shHs[32][HID + 1];
    __shared__ float shRh[32][HID + 1];
    __shared__ int   shRows[32];

    int cnt = g_cnt[j];
    int rb  = blockIdx.x * 32;
    if (rb >= cnt) return;
    int off = g_off[j];
    int t   = threadIdx.x;

    if (t < 32) shRows[t] = (rb + t < cnt) ? g_order[off + rb + t] : -1;
    __syncthreads();

    #pragma unroll
    for (int i = 0; i < 8; i++) {
        int u = t + i * 256;
        int r = u >> 6, cc = u & 63;
        int gr = shRows[r];
        shHs[r][cc] = (gr >= 0) ? g_hs[(size_t)gr * HID + cc] : 0.0f;
    }
    #pragma unroll
    for (int i = 0; i < 16; i++) { int u = t + i * 256; shU[u >> 6][u & 63] = Ur[u]; }
    __syncthreads();

    int c = t & 63, rg = t >> 6;
    float zv[8], hsv[8];

    #pragma unroll
    for (int i = 0; i < 8; i++) {
        int r = rg + 4 * i;
        int gr = shRows[r];
        float s = 0.f;
        #pragma unroll 16
        for (int kk = 0; kk < HID; kk++) s += shHs[r][kk] * shU[kk][c];
        float rj = (gr >= 0) ? sigmoidf_(g_xr[(size_t)gr * HID + c] + s) : 0.0f;
        shRh[r][c] = rj * shHs[r][c];
    }
    __syncthreads();
    #pragma unroll
    for (int i = 0; i < 16; i++) { int u = t + i * 256; shU[u >> 6][u & 63] = Uz[u]; }
    __syncthreads();

    #pragma unroll
    for (int i = 0; i < 8; i++) {
        int r = rg + 4 * i;
        int gr = shRows[r];
        float s = 0.f;
        #pragma unroll 16
        for (int kk = 0; kk < HID; kk++) s += shHs[r][kk] * shU[kk][c];
        zv[i]  = (gr >= 0) ? sigmoidf_(g_xz[(size_t)gr * HID + c] + s) : 0.0f;
        hsv[i] = shHs[r][c];
    }
    __syncthreads();
    #pragma unroll
    for (int i = 0; i < 16; i++) { int u = t + i * 256; shU[u >> 6][u & 63] = Uh[u]; }
    __syncthreads();

    #pragma unroll
    for (int i = 0; i < 8; i++) {
        int r = rg + 4 * i;
        int gr = shRows[r];
        if (gr < 0) continue;
        float s = 0.f;
        #pragma unroll 16
        for (int kk = 0; kk < HID; kk++) s += shRh[r][kk] * shU[kk][c];
        float hh = tanhf(g_xh[(size_t)gr * HID + c] + s);
        float hj = (1.0f - zv[i]) * hsv[i] + zv[i] * hh;
        size_t idx = (size_t)gr * HID + c;
        g_h[idx] = hj;
        __nv_bfloat16 bh = __float2bfloat16(hj);
        g_hbh[idx] = bh;
        g_hbl[idx] = __float2bfloat16(hj - __bfloat162float(bh));
    }
}

// ---------------- root reduce + decode ----------------
__global__ void final_kernel(const float* __restrict__ dec_w,
                             const float* __restrict__ dec_b,
                             float* __restrict__ out)
{
    __shared__ float red[4][HID];
    __shared__ float root[HID];
    int t = threadIdx.x;
    int c = t & 63, q = t >> 6;
    int cnt = g_cnt[0], off = g_off[0];
    float s = 0.f;
    for (int l = q; l < cnt; l += 4) {
        int gr = g_order[off + l];
        s += g_h[(size_t)gr * HID + c];
    }
    red[q][c] = s;
    __syncthreads();
    if (t < HID) root[t] = red[0][t] + red[1][t] + red[2][t] + red[3][t];
    __syncthreads();
    if (t < NCLS) {
        float a = dec_b[t];
        #pragma unroll 16
        for (int k = 0; k < HID; k++) a += root[k] * dec_w[k * NCLS + t];
        out[t] = a;
    }
}

// ---------------- launch ----------------
extern "C" void kernel_launch(void* const* d_in, const int* in_sizes, int n_in,
                              void* d_out, int out_size)
{
    const float* adj   = (const float*)d_in[0];
    const float* tfidf = (const float*)d_in[1];
    const int*   level = (const int*)d_in[2];
    const float* Ew    = (const float*)d_in[3];
    const float* Wr    = (const float*)d_in[4];
    const float* Wz    = (const float*)d_in[5];
    const float* Ur    = (const float*)d_in[6];
    const float* Uz    = (const float*)d_in[7];
    const float* Wh    = (const float*)d_in[8];
    const float* Uh    = (const float*)d_in[9];
    const float* dw    = (const float*)d_in[10];
    const float* db    = (const float*)d_in[11];
    float* out = (float*)d_out;

    k_init<<<1, 32>>>();
    k_zero<<<3072, 256>>>();
    k_hist<<<64, 256>>>(level);
    k_scan<<<1, 1>>>();
    k_scatter<<<64, 256>>>(level);
    embed_kernel<<<N / RROWS, 256>>>(tfidf, Ew, Wr, Wz, Wh);
    for (int j = NLEV - 1; j >= 0; j--) {
        agg_kernel<<<dim3(N / RROWS, KSPLIT), 256>>>(adj, j);
        gru_kernel<<<N / 32, 256>>>(Ur, Uz, Uh, j);
    }
    final_kernel<<<1, 256>>>(dw, db, out);
}

// round 8
// speedup vs baseline: 2.3587x; 1.1506x over previous
#include <cuda_runtime.h>
#include <cuda_bf16.h>
#include <math.h>
#include <stdint.h>

#define N       16384
#define IN_DIM  5000
#define HID     64
#define NCLS    4
#define NLEV    11
#define KSPLIT  16
#define KCHUNK  (N / KSPLIT)               /* 1024 */
#define KT      64
#define STAGES_A (KCHUNK / KT)             /* 16 */
#define STAGES_E ((IN_DIM + KT - 1) / KT)  /* 79 */
#define RROWS   64
#define AGG_BLKS 384
#define GRU_BLKS 128
#define EMB_BLKS (N / RROWS)               /* 256 */

// smem layout offsets (bytes) within the 37120-byte raw buffer
#define OFF_AH   0
#define OFF_AL   9216
#define OFF_BH   18432
#define OFF_BL   27648
#define OFF_ROWS 36864
#define SMEM_RAW 37120

// ---------------- device scratch (static, no allocations) ----------------
__device__ float g_h  [N * HID];
__device__ float g_hs [N * HID];
__device__ float g_xr [N * HID];
__device__ float g_xz [N * HID];
__device__ float g_xh [N * HID];
__device__ __nv_bfloat16 g_hbh[N * HID];   // h hi
__device__ __nv_bfloat16 g_hbl[N * HID];   // h lo (residual)
__device__ int   g_order[N];
__device__ int   g_cnt[NLEV];
__device__ int   g_cur[NLEV];
__device__ int   g_off[NLEV + 1];

__device__ __forceinline__ float sigmoidf_(float x) {
    return 1.0f / (1.0f + expf(-x));
}

// ---------------- mma helpers ----------------
__device__ __forceinline__ uint32_t sptr(const void* p) {
    return (uint32_t)__cvta_generic_to_shared(p);
}
__device__ __forceinline__ void ldsm_x4(uint32_t* r, uint32_t addr) {
    asm volatile("ldmatrix.sync.aligned.m8n8.x4.shared.b16 {%0,%1,%2,%3}, [%4];"
                 : "=r"(r[0]), "=r"(r[1]), "=r"(r[2]), "=r"(r[3]) : "r"(addr));
}
__device__ __forceinline__ void ldsm_x4_t(uint32_t* r, uint32_t addr) {
    asm volatile("ldmatrix.sync.aligned.m8n8.x4.trans.shared.b16 {%0,%1,%2,%3}, [%4];"
                 : "=r"(r[0]), "=r"(r[1]), "=r"(r[2]), "=r"(r[3]) : "r"(addr));
}
__device__ __forceinline__ void mma_bf16(float* c, const uint32_t* a,
                                         uint32_t b0, uint32_t b1) {
    asm volatile("mma.sync.aligned.m16n8k16.row.col.f32.bf16.bf16.f32 "
                 "{%0,%1,%2,%3}, {%4,%5,%6,%7}, {%8,%9}, {%0,%1,%2,%3};"
                 : "+f"(c[0]), "+f"(c[1]), "+f"(c[2]), "+f"(c[3])
                 : "r"(a[0]), "r"(a[1]), "r"(a[2]), "r"(a[3]), "r"(b0), "r"(b1));
}
__device__ __forceinline__ void split2(float x, float y, uint32_t& hi, uint32_t& lo) {
    __nv_bfloat162 h = __floats2bfloat162_rn(x, y);
    float rx = x - __bfloat162float(h.x);
    float ry = y - __bfloat162float(h.y);
    __nv_bfloat162 l = __floats2bfloat162_rn(rx, ry);
    union { __nv_bfloat162 h; uint32_t u; } ch, cl;
    ch.h = h; cl.h = l;
    hi = ch.u; lo = cl.u;
}

#define MMA3(ACC, AHI, ALO, BH0, BH1, BL0, BL1) \
    do { mma_bf16(ACC, AHI, BH0, BH1); mma_bf16(ACC, AHI, BL0, BL1); \
         mma_bf16(ACC, ALO, BH0, BH1); } while (0)

// ---------------- bookkeeping ----------------
__global__ void k_setup() {
    int idx = blockIdx.x * blockDim.x + threadIdx.x;
    if (blockIdx.x == 0 && threadIdx.x < NLEV) {
        g_cnt[threadIdx.x] = 0; g_cur[threadIdx.x] = 0;
    }
    const int NH4 = (N * HID) / 4;     /* 262144 */
    const int HB4 = (N * HID) / 8;     /* 131072 */
    float4 z = make_float4(0.f, 0.f, 0.f, 0.f);
    if (idx < NH4)                 ((float4*)g_hs )[idx]             = z;
    else if (idx < NH4 + HB4)      ((float4*)g_hbh)[idx - NH4]       = z;
    else if (idx < NH4 + 2 * HB4)  ((float4*)g_hbl)[idx - NH4 - HB4] = z;
}

__global__ void k_hist(const int* __restrict__ level) {
    int i = blockIdx.x * blockDim.x + threadIdx.x;
    if (i < N) atomicAdd(&g_cnt[level[i]], 1);
}

__global__ void k_scanscatter(const int* __restrict__ level) {
    int t = threadIdx.x;
    if (t == 0) {
        g_off[0] = 0;
        for (int l = 0; l < NLEV; l++) g_off[l + 1] = g_off[l] + g_cnt[l];
    }
    __syncthreads();
    for (int i = t; i < N; i += blockDim.x) {
        int lv = level[i];
        int p  = atomicAdd(&g_cur[lv], 1);
        g_order[g_off[lv] + p] = i;
    }
}

// ---------------- tile loaders ----------------
__device__ __forceinline__ void load_A_gather(float4* ar, const float* __restrict__ src,
                                              const int* shRows, int t, int k0) {
    #pragma unroll
    for (int i = 0; i < 4; i++) {
        int u = t + i * 256, r = u >> 4, kq = u & 15;
        int grow = shRows[r];
        float4 v = make_float4(0.f, 0.f, 0.f, 0.f);
        if (grow >= 0) v = *(const float4*)(src + (size_t)grow * N + k0 + kq * 4);
        ar[i] = v;
    }
}
__device__ __forceinline__ void load_A_dense(float4* ar, const float* __restrict__ src,
                                             int rowbase, int t, int k0) {
    #pragma unroll
    for (int i = 0; i < 4; i++) {
        int u = t + i * 256, r = u >> 4, kq = u & 15;
        int k = k0 + kq * 4;
        float4 v = make_float4(0.f, 0.f, 0.f, 0.f);
        const float* p = src + (size_t)(rowbase + r) * IN_DIM + k;
        if (k + 3 < IN_DIM) v = *(const float4*)p;
        else if (k < IN_DIM) {
            float tmp[4] = {0.f, 0.f, 0.f, 0.f};
            #pragma unroll
            for (int m = 0; m < 4; m++) if (k + m < IN_DIM) tmp[m] = p[m];
            v = make_float4(tmp[0], tmp[1], tmp[2], tmp[3]);
        }
        ar[i] = v;
    }
}
__device__ __forceinline__ void load_H(uint4* hh, uint4* hl, int t, int k0) {
    #pragma unroll
    for (int i = 0; i < 2; i++) {
        int u = t + i * 256, kr = u >> 3, q = u & 7;
        size_t idx = (size_t)(k0 + kr) * HID + q * 8;
        hh[i] = *(const uint4*)&g_hbh[idx];
        hl[i] = *(const uint4*)&g_hbl[idx];
    }
}
__device__ __forceinline__ void load_E(float4* er, const float* __restrict__ Ew,
                                       int t, int k0) {
    #pragma unroll
    for (int i = 0; i < 4; i++) {
        int u = t + i * 256, kr = u >> 4, kq = u & 15;
        int k = k0 + kr;
        float4 v = make_float4(0.f, 0.f, 0.f, 0.f);
        if (k < IN_DIM) v = *(const float4*)&Ew[(size_t)k * HID + kq * 4];
        er[i] = v;
    }
}

// ---------------- agg body (persistent tiles) ----------------
__device__ void agg_body(const float* __restrict__ adj, int j,
                         unsigned char* sraw, int bid, int nblk)
{
    __nv_bfloat16 (*shAh)[KT + 8]  = (__nv_bfloat16(*)[KT + 8])(sraw + OFF_AH);
    __nv_bfloat16 (*shAl)[KT + 8]  = (__nv_bfloat16(*)[KT + 8])(sraw + OFF_AL);
    __nv_bfloat16 (*shBh)[HID + 8] = (__nv_bfloat16(*)[HID + 8])(sraw + OFF_BH);
    __nv_bfloat16 (*shBl)[HID + 8] = (__nv_bfloat16(*)[HID + 8])(sraw + OFF_BL);
    int* shRows = (int*)(sraw + OFF_ROWS);

    int cnt = g_cnt[j];
    int off = g_off[j];
    int nRow = (cnt + RROWS - 1) / RROWS;
    int ntile = nRow * KSPLIT;
    int t = threadIdx.x;

    int lane = t & 31;
    int wm = (t >> 5) & 3;
    int wn = (t >> 5) >> 2;
    uint32_t aAddrH = sptr(&shAh[wm * 16 + (lane & 15)][(lane >> 4) << 3]);
    uint32_t aAddrL = sptr(&shAl[wm * 16 + (lane & 15)][(lane >> 4) << 3]);
    uint32_t bAddrH = sptr(&shBh[lane & 15][wn * 32 + ((lane >> 4) << 3)]);
    uint32_t bAddrL = sptr(&shBl[lane & 15][wn * 32 + ((lane >> 4) << 3)]);
    const int B_ROW = (HID + 8) * 2;   // 144 bytes
    int g = lane >> 2, tq = lane & 3;

    for (int tile = bid; tile < ntile; tile += nblk) {
        int rbi = tile % nRow;
        int ks  = tile / nRow;
        int rb  = rbi * RROWS;
        int kbase = ks * KCHUNK;

        __syncthreads();
        if (t < RROWS) shRows[t] = (rb + t < cnt) ? g_order[off + rb + t] : -1;
        __syncthreads();

        float4 ar[4];
        uint4  hh[2], hl[2];
        load_A_gather(ar, adj, shRows, t, kbase);
        load_H(hh, hl, t, kbase);

        float acc[4][4] = {};

        for (int s = 0; s < STAGES_A; s++) {
            #pragma unroll
            for (int i = 0; i < 4; i++) {
                int u = t + i * 256, r = u >> 4, kq = u & 15;
                uint32_t h0, l0, h1, l1;
                split2(ar[i].x, ar[i].y, h0, l0);
                split2(ar[i].z, ar[i].w, h1, l1);
                *(uint2*)&shAh[r][kq * 4] = make_uint2(h0, h1);
                *(uint2*)&shAl[r][kq * 4] = make_uint2(l0, l1);
            }
            #pragma unroll
            for (int i = 0; i < 2; i++) {
                int u = t + i * 256, kr = u >> 3, q = u & 7;
                *(uint4*)&shBh[kr][q * 8] = hh[i];
                *(uint4*)&shBl[kr][q * 8] = hl[i];
            }
            __syncthreads();
            if (s + 1 < STAGES_A) {
                int k0 = kbase + (s + 1) * KT;
                load_A_gather(ar, adj, shRows, t, k0);
                load_H(hh, hl, t, k0);
            }
            #pragma unroll
            for (int kss = 0; kss < KT / 16; kss++) {
                uint32_t ah[4], al[4];
                ldsm_x4(ah, aAddrH + kss * 32);
                ldsm_x4(al, aAddrL + kss * 32);
                uint32_t bh[4], bl[4];
                ldsm_x4_t(bh, bAddrH + kss * 16 * B_ROW);
                ldsm_x4_t(bl, bAddrL + kss * 16 * B_ROW);
                MMA3(acc[0], ah, al, bh[0], bh[1], bl[0], bl[1]);
                MMA3(acc[1], ah, al, bh[2], bh[3], bl[2], bl[3]);
                ldsm_x4_t(bh, bAddrH + kss * 16 * B_ROW + 32);
                ldsm_x4_t(bl, bAddrL + kss * 16 * B_ROW + 32);
                MMA3(acc[2], ah, al, bh[0], bh[1], bl[0], bl[1]);
                MMA3(acc[3], ah, al, bh[2], bh[3], bl[2], bl[3]);
            }
            __syncthreads();
        }

        #pragma unroll
        for (int nb = 0; nb < 4; nb++) {
            int col = wn * 32 + nb * 8 + tq * 2;
            int r0 = wm * 16 + g;
            int gr0 = shRows[r0];
            if (gr0 >= 0) {
                atomicAdd(&g_hs[(size_t)gr0 * HID + col],     acc[nb][0]);
                atomicAdd(&g_hs[(size_t)gr0 * HID + col + 1], acc[nb][1]);
            }
            int gr1 = shRows[r0 + 8];
            if (gr1 >= 0) {
                atomicAdd(&g_hs[(size_t)gr1 * HID + col],     acc[nb][2]);
                atomicAdd(&g_hs[(size_t)gr1 * HID + col + 1], acc[nb][3]);
            }
        }
    }
}

// ---------------- embed body ----------------
__device__ void embed_body(const float* __restrict__ tfidf, const float* __restrict__ Ew,
                           const float* __restrict__ Wr, const float* __restrict__ Wz,
                           const float* __restrict__ Wh,
                           unsigned char* sraw, int rowblock)
{
    __nv_bfloat16 (*shAh)[KT + 8]  = (__nv_bfloat16(*)[KT + 8])(sraw + OFF_AH);
    __nv_bfloat16 (*shAl)[KT + 8]  = (__nv_bfloat16(*)[KT + 8])(sraw + OFF_AL);
    __nv_bfloat16 (*shBh)[HID + 8] = (__nv_bfloat16(*)[HID + 8])(sraw + OFF_BH);
    __nv_bfloat16 (*shBl)[HID + 8] = (__nv_bfloat16(*)[HID + 8])(sraw + OFF_BL);
    float (*shX)[68] = (float(*)[68])(sraw);            // 17408 B
    float (*shW)[64] = (float(*)[64])(sraw + OFF_BH);   // 16384 B

    int t = threadIdx.x;
    int rowbase = rowblock * RROWS;

    int lane = t & 31;
    int wm = (t >> 5) & 3;
    int wn = (t >> 5) >> 2;
    uint32_t aAddrH = sptr(&shAh[wm * 16 + (lane & 15)][(lane >> 4) << 3]);
    uint32_t aAddrL = sptr(&shAl[wm * 16 + (lane & 15)][(lane >> 4) << 3]);
    uint32_t bAddrH = sptr(&shBh[lane & 15][wn * 32 + ((lane >> 4) << 3)]);
    uint32_t bAddrL = sptr(&shBl[lane & 15][wn * 32 + ((lane >> 4) << 3)]);
    const int B_ROW = (HID + 8) * 2;

    float4 ar[4], er[4];
    load_A_dense(ar, tfidf, rowbase, t, 0);
    load_E(er, Ew, t, 0);

    float acc[4][4] = {};

    for (int s = 0; s < STAGES_E; s++) {
        #pragma unroll
        for (int i = 0; i < 4; i++) {
            int u = t + i * 256, r = u >> 4, kq = u & 15;
            uint32_t h0, l0, h1, l1;
            split2(ar[i].x, ar[i].y, h0, l0);
            split2(ar[i].z, ar[i].w, h1, l1);
            *(uint2*)&shAh[r][kq * 4] = make_uint2(h0, h1);
            *(uint2*)&shAl[r][kq * 4] = make_uint2(l0, l1);
        }
        #pragma unroll
        for (int i = 0; i < 4; i++) {
            int u = t + i * 256, kr = u >> 4, kq = u & 15;
            uint32_t h0, l0, h1, l1;
            split2(er[i].x, er[i].y, h0, l0);
            split2(er[i].z, er[i].w, h1, l1);
            *(uint2*)&shBh[kr][kq * 4] = make_uint2(h0, h1);
            *(uint2*)&shBl[kr][kq * 4] = make_uint2(l0, l1);
        }
        __syncthreads();
        if (s + 1 < STAGES_E) {
            int k0 = (s + 1) * KT;
            load_A_dense(ar, tfidf, rowbase, t, k0);
            load_E(er, Ew, t, k0);
        }
        #pragma unroll
        for (int kss = 0; kss < KT / 16; kss++) {
            uint32_t ah[4], al[4];
            ldsm_x4(ah, aAddrH + kss * 32);
            ldsm_x4(al, aAddrL + kss * 32);
            uint32_t bh[4], bl[4];
            ldsm_x4_t(bh, bAddrH + kss * 16 * B_ROW);
            ldsm_x4_t(bl, bAddrL + kss * 16 * B_ROW);
            MMA3(acc[0], ah, al, bh[0], bh[1], bl[0], bl[1]);
            MMA3(acc[1], ah, al, bh[2], bh[3], bl[2], bl[3]);
            ldsm_x4_t(bh, bAddrH + kss * 16 * B_ROW + 32);
            ldsm_x4_t(bl, bAddrL + kss * 16 * B_ROW + 32);
            MMA3(acc[2], ah, al, bh[0], bh[1], bl[0], bl[1]);
            MMA3(acc[3], ah, al, bh[2], bh[3], bl[2], bl[3]);
        }
        __syncthreads();
    }

    int g = lane >> 2, tq = lane & 3;
    #pragma unroll
    for (int nb = 0; nb < 4; nb++) {
        int col = wn * 32 + nb * 8 + tq * 2;
        int r0 = wm * 16 + g;
        shX[r0][col]         = acc[nb][0];
        shX[r0][col + 1]     = acc[nb][1];
        shX[r0 + 8][col]     = acc[nb][2];
        shX[r0 + 8][col + 1] = acc[nb][3];
    }

    const float* Ws[3] = {Wr, Wz, Wh};
    float*       Os[3] = {g_xr, g_xz, g_xh};
    int cq = t & 15, rq = t >> 4;
    int c0 = cq * 4, r0 = rq * 4;
    #pragma unroll
    for (int w = 0; w < 3; w++) {
        __syncthreads();
        #pragma unroll
        for (int i = 0; i < 4; i++) {
            int u = t + i * 256;
            int kk = u >> 4, c4 = (u & 15) * 4;
            *(float4*)&shW[kk][c4] = *(const float4*)&Ws[w][(size_t)kk * HID + c4];
        }
        __syncthreads();
        float o[4][4] = {};
        #pragma unroll 16
        for (int kk = 0; kk < HID; kk++) {
            float4 b = *(float4*)&shW[kk][c0];
            float a[4];
            #pragma unroll
            for (int i = 0; i < 4; i++) a[i] = shX[r0 + i][kk];
            #pragma unroll
            for (int i = 0; i < 4; i++) {
                o[i][0] += a[i] * b.x; o[i][1] += a[i] * b.y;
                o[i][2] += a[i] * b.z; o[i][3] += a[i] * b.w;
            }
        }
        #pragma unroll
        for (int i = 0; i < 4; i++)
            *(float4*)&Os[w][(size_t)(rowbase + r0 + i) * HID + c0] =
                make_float4(o[i][0], o[i][1], o[i][2], o[i][3]);
    }
}

// ---------------- kernels ----------------
// fused: embed (blocks [0,EMB_BLKS)) + agg level 10 (blocks [EMB_BLKS, +AGG_BLKS))
__global__ __launch_bounds__(256) void fat_kernel(
    const float* __restrict__ adj, const float* __restrict__ tfidf,
    const float* __restrict__ Ew, const float* __restrict__ Wr,
    const float* __restrict__ Wz, const float* __restrict__ Wh)
{
    __shared__ __align__(16) unsigned char sraw[SMEM_RAW];
    int bx = blockIdx.x;
    if (bx < EMB_BLKS) embed_body(tfidf, Ew, Wr, Wz, Wh, sraw, bx);
    else               agg_body(adj, NLEV - 1, sraw, bx - EMB_BLKS, AGG_BLKS);
}

__global__ __launch_bounds__(256) void agg_kernel(const float* __restrict__ adj, int j)
{
    __shared__ __align__(16) unsigned char sraw[SMEM_RAW];
    agg_body(adj, j, sraw, blockIdx.x, AGG_BLKS);
}

// ---------------- GRU cell (persistent over 32-row tiles) ----------------
__global__ __launch_bounds__(256) void gru_kernel(
    const float* __restrict__ Ur, const float* __restrict__ Uz,
    const float* __restrict__ Uh, int j)
{
    __shared__ float shU [HID][HID + 1];
    __shared__ float shHs[32][HID + 1];
    __shared__ float shRh[32][HID + 1];
    __shared__ int   shRows[32];

    int cnt = g_cnt[j];
    int off = g_off[j];
    int ntile = (cnt + 31) >> 5;
    int t = threadIdx.x;
    int c = t & 63, rg = t >> 6;

    for (int tile = blockIdx.x; tile < ntile; tile += GRU_BLKS) {
        int rb = tile * 32;
        __syncthreads();
        if (t < 32) shRows[t] = (rb + t < cnt) ? g_order[off + rb + t] : -1;
        __syncthreads();

        #pragma unroll
        for (int i = 0; i < 8; i++) {
            int u = t + i * 256;
            int r = u >> 6, cc = u & 63;
            int gr = shRows[r];
            shHs[r][cc] = (gr >= 0) ? g_hs[(size_t)gr * HID + cc] : 0.0f;
        }
        #pragma unroll
        for (int i = 0; i < 16; i++) { int u = t + i * 256; shU[u >> 6][u & 63] = Ur[u]; }
        __syncthreads();

        float zv[8], hsv[8];

        #pragma unroll
        for (int i = 0; i < 8; i++) {
            int r = rg + 4 * i;
            int gr = shRows[r];
            float s = 0.f;
            #pragma unroll 16
            for (int kk = 0; kk < HID; kk++) s += shHs[r][kk] * shU[kk][c];
            float rj = (gr >= 0) ? sigmoidf_(g_xr[(size_t)gr * HID + c] + s) : 0.0f;
            shRh[r][c] = rj * shHs[r][c];
        }
        __syncthreads();
        #pragma unroll
        for (int i = 0; i < 16; i++) { int u = t + i * 256; shU[u >> 6][u & 63] = Uz[u]; }
        __syncthreads();

        #pragma unroll
        for (int i = 0; i < 8; i++) {
            int r = rg + 4 * i;
            int gr = shRows[r];
            float s = 0.f;
            #pragma unroll 16
            for (int kk = 0; kk < HID; kk++) s += shHs[r][kk] * shU[kk][c];
            zv[i]  = (gr >= 0) ? sigmoidf_(g_xz[(size_t)gr * HID + c] + s) : 0.0f;
            hsv[i] = shHs[r][c];
        }
        __syncthreads();
        #pragma unroll
        for (int i = 0; i < 16; i++) { int u = t + i * 256; shU[u >> 6][u & 63] = Uh[u]; }
        __syncthreads();

        #pragma unroll
        for (int i = 0; i < 8; i++) {
            int r = rg + 4 * i;
            int gr = shRows[r];
            if (gr < 0) continue;
            float s = 0.f;
            #pragma unroll 16
            for (int kk = 0; kk < HID; kk++) s += shRh[r][kk] * shU[kk][c];
            float hh = tanhf(g_xh[(size_t)gr * HID + c] + s);
            float hj = (1.0f - zv[i]) * hsv[i] + zv[i] * hh;
            size_t idx = (size_t)gr * HID + c;
            g_h[idx] = hj;
            __nv_bfloat16 bh = __float2bfloat16(hj);
            g_hbh[idx] = bh;
            g_hbl[idx] = __float2bfloat16(hj - __bfloat162float(bh));
        }
    }
}

// ---------------- root reduce + decode ----------------
__global__ void final_kernel(const float* __restrict__ dec_w,
                             const float* __restrict__ dec_b,
                             float* __restrict__ out)
{
    __shared__ float red[4][HID];
    __shared__ float root[HID];
    int t = threadIdx.x;
    int c = t & 63, q = t >> 6;
    int cnt = g_cnt[0], off = g_off[0];
    float s = 0.f;
    for (int l = q; l < cnt; l += 4) {
        int gr = g_order[off + l];
        s += g_h[(size_t)gr * HID + c];
    }
    red[q][c] = s;
    __syncthreads();
    if (t < HID) root[t] = red[0][t] + red[1][t] + red[2][t] + red[3][t];
    __syncthreads();
    if (t < NCLS) {
        float a = dec_b[t];
        #pragma unroll 16
        for (int k = 0; k < HID; k++) a += root[k] * dec_w[k * NCLS + t];
        out[t] = a;
    }
}

// ---------------- launch ----------------
extern "C" void kernel_launch(void* const* d_in, const int* in_sizes, int n_in,
                              void* d_out, int out_size)
{
    const float* adj   = (const float*)d_in[0];
    const float* tfidf = (const float*)d_in[1];
    const int*   level = (const int*)d_in[2];
    const float* Ew    = (const float*)d_in[3];
    const float* Wr    = (const float*)d_in[4];
    const float* Wz    = (const float*)d_in[5];
    const float* Ur    = (const float*)d_in[6];
    const float* Uz    = (const float*)d_in[7];
    const float* Wh    = (const float*)d_in[8];
    const float* Uh    = (const float*)d_in[9];
    const float* dw    = (const float*)d_in[10];
    const float* db    = (const float*)d_in[11];
    float* out = (float*)d_out;

    k_setup<<<2048, 256>>>();
    k_hist<<<64, 256>>>(level);
    k_scanscatter<<<1, 1024>>>(level);
    // index 3: embed + agg(level 10) fused — fills the whole chip
    fat_kernel<<<EMB_BLKS + AGG_BLKS, 256>>>(adj, tfidf, Ew, Wr, Wz, Wh);
    gru_kernel<<<GRU_BLKS, 256>>>(Ur, Uz, Uh, NLEV - 1);
    for (int j = NLEV - 2; j >= 0; j--) {
        agg_kernel<<<AGG_BLKS, 256>>>(adj, j);
        gru_kernel<<<GRU_BLKS, 256>>>(Ur, Uz, Uh, j);
    }
    final_kernel<<<1, 256>>>(dw, db, out);
}